// round 1
// baseline (speedup 1.0000x reference)
#include <cuda_runtime.h>
#include <math.h>

#define BATCH   16384
#define LATENT  64
#define HID     512
#define OUTD    256
#define KEXP    (HID * 9)   // 4608: 1 silu + 8 spline bases per input unit

// ---------------- scratch (device globals; allocation-free rule) ------------
__device__ float g_h  [(size_t)BATCH * HID];        //  33.5 MB activations
__device__ float g_phi[(size_t)BATCH * KEXP];       // 302   MB expanded features
__device__ float g_Wd [(size_t)LATENT * HID];       //  dense_w transposed (K x N)
__device__ float g_W1 [(size_t)KEXP * HID];         //  combined layer-1 weight (K x N)
__device__ float g_W2 [(size_t)KEXP * OUTD];        //  combined layer-2 weight (K x N)

// ---------------- weight prep ----------------------------------------------
__global__ void prep_dense(const float* __restrict__ dw, float* __restrict__ Wd) {
    int idx = blockIdx.x * blockDim.x + threadIdx.x;
    if (idx >= LATENT * HID) return;
    int k = idx / HID, n = idx % HID;
    Wd[(size_t)k * HID + n] = dw[(size_t)n * LATENT + k];
}

// Wt[(i*9+0)*N + o] = base_w[o][i]; Wt[(i*9+1+g)*N + o] = spline_w[o][i][g]*scaler[o][i]
__global__ void prep_kan(const float* __restrict__ bw, const float* __restrict__ sw,
                         const float* __restrict__ sc, float* __restrict__ Wt, int N) {
    int idx = blockIdx.x * blockDim.x + threadIdx.x;
    if (idx >= N * HID) return;
    int o = idx / HID, i = idx % HID;
    float s = sc[(size_t)o * HID + i];
    Wt[((size_t)(i * 9 + 0)) * N + o] = bw[(size_t)o * HID + i];
#pragma unroll
    for (int g = 0; g < 8; g++)
        Wt[((size_t)(i * 9 + 1 + g)) * N + o] = sw[((size_t)o * HID + i) * 8 + g] * s;
}

// ---------------- expand: h -> [silu(h), B-splines(h)] ----------------------
__global__ void expand_kernel(const float* __restrict__ h, float* __restrict__ phi) {
    int idx = blockIdx.x * blockDim.x + threadIdx.x;
    if (idx >= BATCH * HID) return;
    float xv = h[idx];

    // grid[j] = (j-3)*0.4f - 1.0f, computed mul-then-add (match JAX, no FMA fuse)
    float g[12];
#pragma unroll
    for (int j = 0; j < 12; j++)
        g[j] = __fadd_rn(__fmul_rn((float)(j - 3), 0.4f), -1.0f);

    float bas[11];
#pragma unroll
    for (int j = 0; j < 11; j++)
        bas[j] = (xv >= g[j] && xv < g[j + 1]) ? 1.0f : 0.0f;

#pragma unroll
    for (int k = 1; k <= 3; k++) {
#pragma unroll
        for (int j = 0; j < 11 - k; j++) {
            float left  = (xv - g[j])       / (g[j + k]     - g[j])     * bas[j];
            float right = (g[j + k + 1] - xv) / (g[j + k + 1] - g[j + 1]) * bas[j + 1];
            bas[j] = left + right;
        }
    }

    float si = xv / (1.0f + expf(-xv));
    size_t base = (size_t)idx * 9;       // == b*4608 + i*9
    phi[base] = si;
#pragma unroll
    for (int gg = 0; gg < 8; gg++) phi[base + 1 + gg] = bas[gg];
}

// ---------------- tiled fp32 SGEMM: C = A(MxK) * B(KxN) ---------------------
// EPI==1: C = silu(C + bias[col])
template <int EPI>
__global__ __launch_bounds__(256) void sgemm_kernel(
    const float* __restrict__ A, const float* __restrict__ Bm,
    const float* __restrict__ bias, float* __restrict__ C,
    int M, int N, int K)
{
    constexpr int BK = 16;
    __shared__ float As[BK][128];
    __shared__ float Bs[BK][128];

    const int tid = threadIdx.x;
    const int tx = tid & 15;       // 16 cols of threads
    const int ty = tid >> 4;       // 16 rows of threads
    const int bm = blockIdx.y * 128;
    const int bn = blockIdx.x * 128;

    float acc[8][8];
#pragma unroll
    for (int i = 0; i < 8; i++)
#pragma unroll
        for (int j = 0; j < 8; j++) acc[i][j] = 0.0f;

    for (int k0 = 0; k0 < K; k0 += BK) {
#pragma unroll
        for (int it = 0; it < 2; it++) {
            int f4 = tid + it * 256;
            // A tile: 128 rows x 16 cols = 512 float4 (4 per row)
            int ar = f4 >> 2, ac = (f4 & 3) << 2;
            float4 va = *(const float4*)(A + (size_t)(bm + ar) * K + k0 + ac);
            As[ac + 0][ar] = va.x; As[ac + 1][ar] = va.y;
            As[ac + 2][ar] = va.z; As[ac + 3][ar] = va.w;
            // B tile: 16 rows x 128 cols = 512 float4 (32 per row)
            int br = f4 >> 5, bc = (f4 & 31) << 2;
            float4 vb = *(const float4*)(Bm + (size_t)(k0 + br) * N + bn + bc);
            *(float4*)&Bs[br][bc] = vb;
        }
        __syncthreads();

#pragma unroll
        for (int kk = 0; kk < BK; kk++) {
            float a[8], b[8];
#pragma unroll
            for (int i = 0; i < 8; i++) a[i] = As[kk][ty * 8 + i];
#pragma unroll
            for (int j = 0; j < 8; j++) b[j] = Bs[kk][tx * 8 + j];
#pragma unroll
            for (int i = 0; i < 8; i++)
#pragma unroll
                for (int j = 0; j < 8; j++) acc[i][j] += a[i] * b[j];
        }
        __syncthreads();
    }

#pragma unroll
    for (int i = 0; i < 8; i++) {
        int row = bm + ty * 8 + i;
#pragma unroll
        for (int j = 0; j < 8; j++) {
            int col = bn + tx * 8 + j;
            float v = acc[i][j];
            if (EPI == 1) {
                v += bias[col];
                v = v / (1.0f + expf(-v));
            }
            C[(size_t)row * N + col] = v;
        }
    }
}

// ---------------- launch -----------------------------------------------------
extern "C" void kernel_launch(void* const* d_in, const int* in_sizes, int n_in,
                              void* d_out, int out_size) {
    const float* x   = (const float*)d_in[0];
    const float* dw  = (const float*)d_in[1];
    const float* db  = (const float*)d_in[2];
    const float* bw1 = (const float*)d_in[3];
    const float* sw1 = (const float*)d_in[4];
    const float* sc1 = (const float*)d_in[5];
    const float* bw2 = (const float*)d_in[6];
    const float* sw2 = (const float*)d_in[7];
    const float* sc2 = (const float*)d_in[8];
    float* out = (float*)d_out;

    float *p_h, *p_phi, *p_Wd, *p_W1, *p_W2;
    cudaGetSymbolAddress((void**)&p_h,   g_h);
    cudaGetSymbolAddress((void**)&p_phi, g_phi);
    cudaGetSymbolAddress((void**)&p_Wd,  g_Wd);
    cudaGetSymbolAddress((void**)&p_W1,  g_W1);
    cudaGetSymbolAddress((void**)&p_W2,  g_W2);

    // weight prep (cheap, every call for determinism)
    prep_dense<<<(LATENT * HID + 255) / 256, 256>>>(dw, p_Wd);
    prep_kan<<<(HID * HID + 255) / 256, 256>>>(bw1, sw1, sc1, p_W1, HID);
    prep_kan<<<(OUTD * HID + 255) / 256, 256>>>(bw2, sw2, sc2, p_W2, OUTD);

    dim3 blk(256);
    dim3 gDense(HID / 128, BATCH / 128);
    dim3 gL1(HID / 128, BATCH / 128);
    dim3 gL2(OUTD / 128, BATCH / 128);
    int expBlocks = (BATCH * HID + 255) / 256;

    // h0 = silu(x @ Wd + b)
    sgemm_kernel<1><<<gDense, blk>>>(x, p_Wd, db, p_h, BATCH, HID, LATENT);
    // layer 1
    expand_kernel<<<expBlocks, 256>>>(p_h, p_phi);
    sgemm_kernel<0><<<gL1, blk>>>(p_phi, p_W1, nullptr, p_h, BATCH, HID, KEXP);
    // layer 2
    expand_kernel<<<expBlocks, 256>>>(p_h, p_phi);
    sgemm_kernel<0><<<gL2, blk>>>(p_phi, p_W2, nullptr, out, BATCH, OUTD, KEXP);
}

// round 3
// speedup vs baseline: 2.7237x; 2.7237x over previous
#include <cuda_runtime.h>
#include <math.h>
#include <stdint.h>

#define BATCH   16384
#define LATENT  64
#define HID     512
#define OUTD    256
#define KEXP    (HID * 9)   // 4608
#define NCHUNK  (KEXP / 32) // 144

// ---------------- scratch (device globals; allocation-free rule) ------------
__device__ float g_h  [(size_t)BATCH * HID];
__device__ float g_phi[(size_t)BATCH * KEXP];          // tf32-rounded features
__device__ float g_Wd [(size_t)LATENT * HID];          // dense_w (K x N) for prelude
__device__ float g_W1 [(size_t)HID  * KEXP];           // layer1 W (N x K, K-major, tf32)
__device__ float g_W2 [(size_t)OUTD * KEXP];           // layer2 W (N x K, K-major, tf32)

// ---------------- helpers -----------------------------------------------------
__device__ __forceinline__ uint32_t smem_u32(const void* p) {
    uint32_t a;
    asm("{ .reg .u64 t; cvta.to.shared.u64 t, %1; cvt.u32.u64 %0, t; }" : "=r"(a) : "l"(p));
    return a;
}
__device__ __forceinline__ float f_tf32(float v) {
    uint32_t r;
    asm("cvt.rna.tf32.f32 %0, %1;" : "=r"(r) : "f"(v));
    return __uint_as_float(r);
}
__device__ __forceinline__ void cp16(uint32_t dst, const void* src) {
    asm volatile("cp.async.cg.shared.global [%0], [%1], 16;" :: "r"(dst), "l"(src));
}
__device__ __forceinline__ void mma_tf32(float* d, const uint32_t* a, uint32_t b0, uint32_t b1) {
    asm volatile(
        "mma.sync.aligned.m16n8k8.row.col.f32.tf32.tf32.f32 "
        "{%0,%1,%2,%3}, {%4,%5,%6,%7}, {%8,%9}, {%0,%1,%2,%3};"
        : "+f"(d[0]), "+f"(d[1]), "+f"(d[2]), "+f"(d[3])
        : "r"(a[0]), "r"(a[1]), "r"(a[2]), "r"(a[3]), "r"(b0), "r"(b1));
}

// ---------------- weight prep ------------------------------------------------
__global__ void prep_dense(const float* __restrict__ dw, float* __restrict__ Wd) {
    int idx = blockIdx.x * blockDim.x + threadIdx.x;
    if (idx >= LATENT * HID) return;
    int k = idx / HID, n = idx % HID;
    Wd[(size_t)k * HID + n] = dw[(size_t)n * LATENT + k];
}
// N x K, K-major, tf32-rounded
__global__ void prep_kan(const float* __restrict__ bw, const float* __restrict__ sw,
                         const float* __restrict__ sc, float* __restrict__ Wt, int N) {
    int idx = blockIdx.x * blockDim.x + threadIdx.x;
    if (idx >= N * HID) return;
    int o = idx / HID, i = idx % HID;
    float s = sc[(size_t)o * HID + i];
    size_t base = (size_t)o * KEXP + (size_t)i * 9;
    Wt[base] = f_tf32(bw[(size_t)o * HID + i]);
#pragma unroll
    for (int g = 0; g < 8; g++)
        Wt[base + 1 + g] = f_tf32(sw[((size_t)o * HID + i) * 8 + g] * s);
}

// ---------------- expand: h -> [silu(h), B-splines(h)] (tf32-rounded) --------
__global__ void expand_kernel(const float* __restrict__ h, float* __restrict__ phi) {
    int idx = blockIdx.x * blockDim.x + threadIdx.x;
    if (idx >= BATCH * HID) return;
    float xv = h[idx];

    float g[12];
#pragma unroll
    for (int j = 0; j < 12; j++)
        g[j] = __fadd_rn(__fmul_rn((float)(j - 3), 0.4f), -1.0f);

    float bas[11];
#pragma unroll
    for (int j = 0; j < 11; j++)
        bas[j] = (xv >= g[j] && xv < g[j + 1]) ? 1.0f : 0.0f;
#pragma unroll
    for (int k = 1; k <= 3; k++) {
#pragma unroll
        for (int j = 0; j < 11 - k; j++) {
            float left  = (xv - g[j])         / (g[j + k]     - g[j])     * bas[j];
            float right = (g[j + k + 1] - xv) / (g[j + k + 1] - g[j + 1]) * bas[j + 1];
            bas[j] = left + right;
        }
    }
    float si = xv / (1.0f + expf(-xv));
    size_t base = (size_t)idx * 9;
    phi[base] = f_tf32(si);
#pragma unroll
    for (int gg = 0; gg < 8; gg++) phi[base + 1 + gg] = f_tf32(bas[gg]);
}

// ---------------- prelude fp32 SGEMM (K=64): C = silu(A*B + bias) ------------
__global__ __launch_bounds__(256) void sgemm_pre(
    const float* __restrict__ A, const float* __restrict__ Bm,
    const float* __restrict__ bias, float* __restrict__ C, int M, int N, int K)
{
    constexpr int BK = 16;
    __shared__ float As[BK][128];
    __shared__ float Bs[BK][128];
    const int tid = threadIdx.x;
    const int tx = tid & 15, ty = tid >> 4;
    const int bm = blockIdx.y * 128, bn = blockIdx.x * 128;
    float acc[8][8];
#pragma unroll
    for (int i = 0; i < 8; i++)
#pragma unroll
        for (int j = 0; j < 8; j++) acc[i][j] = 0.0f;

    for (int k0 = 0; k0 < K; k0 += BK) {
#pragma unroll
        for (int it = 0; it < 2; it++) {
            int f4 = tid + it * 256;
            int ar = f4 >> 2, ac = (f4 & 3) << 2;
            float4 va = *(const float4*)(A + (size_t)(bm + ar) * K + k0 + ac);
            As[ac + 0][ar] = va.x; As[ac + 1][ar] = va.y;
            As[ac + 2][ar] = va.z; As[ac + 3][ar] = va.w;
            int br = f4 >> 5, bc = (f4 & 31) << 2;
            *(float4*)&Bs[br][bc] = *(const float4*)(Bm + (size_t)(k0 + br) * N + bn + bc);
        }
        __syncthreads();
#pragma unroll
        for (int kk = 0; kk < BK; kk++) {
            float a[8], b[8];
#pragma unroll
            for (int i = 0; i < 8; i++) a[i] = As[kk][ty * 8 + i];
#pragma unroll
            for (int j = 0; j < 8; j++) b[j] = Bs[kk][tx * 8 + j];
#pragma unroll
            for (int i = 0; i < 8; i++)
#pragma unroll
                for (int j = 0; j < 8; j++) acc[i][j] += a[i] * b[j];
        }
        __syncthreads();
    }
#pragma unroll
    for (int i = 0; i < 8; i++) {
        int row = bm + ty * 8 + i;
#pragma unroll
        for (int j = 0; j < 8; j++) {
            int col = bn + tx * 8 + j;
            float v = acc[i][j] + bias[col];
            C[(size_t)row * N + col] = v / (1.0f + expf(-v));
        }
    }
}

// ---------------- tf32 mma.sync GEMM: C[M,N] = A[M,K] * W[N,K]^T --------------
// Block 128x256, BK=32, 512 threads (16 warps, 4x4), warp tile 32x64.
// SMEM: double-buffered, pitch 36 floats (bank-conflict-free fragments).
#define PITCH   36
#define A_FLT   (128 * PITCH)            // 4608 floats
#define B_FLT   (256 * PITCH)            // 9216 floats
#define BUF_FLT (A_FLT + B_FLT)          // 13824 floats
#define SMEM_BYTES (2 * BUF_FLT * 4)     // 110592

__global__ __launch_bounds__(512, 1) void gemm_mma(
    const float* __restrict__ A, const float* __restrict__ W,
    float* __restrict__ C, int N)
{
    extern __shared__ __align__(16) float sm[];
    uint32_t* smu = (uint32_t*)sm;
    const uint32_t sbase = smem_u32(sm);

    const int tid   = threadIdx.x;
    const int wid   = tid >> 5, lane = tid & 31;
    const int g     = lane >> 2, t = lane & 3;
    const int wm    = wid & 3;          // warp row (x32)
    const int wn    = wid >> 2;         // warp col (x64)
    const int bm    = blockIdx.y * 128;
    const int bn    = blockIdx.x * 256;
    const int K     = KEXP;

    // per-thread global src pointers (advance 32 floats per chunk)
    const int av = tid;                  // A vectors: tid, tid+512  (1024 total)
    const int ar0 = av >> 3,        ac0 = (av & 7) << 2;
    const int ar1 = (av + 512) >> 3, ac1 = ((av + 512) & 7) << 2;
    const float* aSrc0 = A + (size_t)(bm + ar0) * K + ac0;
    const float* aSrc1 = A + (size_t)(bm + ar1) * K + ac1;
    const float* bSrc[4];
    int bn_[4], bc_[4];
#pragma unroll
    for (int i = 0; i < 4; i++) {
        int v = tid + i * 512;
        bn_[i] = v >> 3; bc_[i] = (v & 7) << 2;
        bSrc[i] = W + (size_t)(bn + bn_[i]) * K + bc_[i];
    }
    // smem dst offsets (bytes) per buffer
    uint32_t aDst0 = (ar0 * PITCH + ac0) * 4;
    uint32_t aDst1 = (ar1 * PITCH + ac1) * 4;
    uint32_t bDst[4];
#pragma unroll
    for (int i = 0; i < 4; i++) bDst[i] = (A_FLT + bn_[i] * PITCH + bc_[i]) * 4;

    float acc[2][8][4];
#pragma unroll
    for (int mt = 0; mt < 2; mt++)
#pragma unroll
        for (int nt = 0; nt < 8; nt++)
#pragma unroll
            for (int i = 0; i < 4; i++) acc[mt][nt][i] = 0.0f;

    // prologue: load chunks 0,1
#pragma unroll
    for (int c = 0; c < 2; c++) {
        uint32_t bb = sbase + c * BUF_FLT * 4;
        cp16(bb + aDst0, aSrc0 + c * 32);
        cp16(bb + aDst1, aSrc1 + c * 32);
#pragma unroll
        for (int i = 0; i < 4; i++) cp16(bb + bDst[i], bSrc[i] + c * 32);
        asm volatile("cp.async.commit_group;");
    }

    for (int c = 0; c < NCHUNK; c++) {
        const int buf = c & 1;
        asm volatile("cp.async.wait_group 1;");
        __syncthreads();

        const int sa = buf * BUF_FLT;                    // A tile base (floats)
        const int sb = buf * BUF_FLT + A_FLT;            // B tile base
#pragma unroll
        for (int kt = 0; kt < 4; kt++) {
            const int kk = kt * 8 + t;
            uint32_t a[2][4];
#pragma unroll
            for (int mt = 0; mt < 2; mt++) {
                int r0 = wm * 32 + mt * 16 + g;
                a[mt][0] = smu[sa + r0 * PITCH + kk];
                a[mt][1] = smu[sa + (r0 + 8) * PITCH + kk];
                a[mt][2] = smu[sa + r0 * PITCH + kk + 4];
                a[mt][3] = smu[sa + (r0 + 8) * PITCH + kk + 4];
            }
#pragma unroll
            for (int nt = 0; nt < 8; nt++) {
                int n0 = wn * 64 + nt * 8 + g;
                uint32_t b0 = smu[sb + n0 * PITCH + kk];
                uint32_t b1 = smu[sb + n0 * PITCH + kk + 4];
                mma_tf32(acc[0][nt], a[0], b0, b1);
                mma_tf32(acc[1][nt], a[1], b0, b1);
            }
        }
        __syncthreads();

        // issue loads for chunk c+2 into this buffer
        if (c + 2 < NCHUNK) {
            uint32_t bb = sbase + buf * BUF_FLT * 4;
            int off = (c + 2) * 32;
            cp16(bb + aDst0, aSrc0 + off);
            cp16(bb + aDst1, aSrc1 + off);
#pragma unroll
            for (int i = 0; i < 4; i++) cp16(bb + bDst[i], bSrc[i] + off);
        }
        asm volatile("cp.async.commit_group;");
    }

    // epilogue
#pragma unroll
    for (int mt = 0; mt < 2; mt++) {
        int row = bm + wm * 32 + mt * 16 + g;
#pragma unroll
        for (int nt = 0; nt < 8; nt++) {
            int col = bn + wn * 64 + nt * 8 + 2 * t;
            *(float2*)(C + (size_t)row * N + col) =
                make_float2(acc[mt][nt][0], acc[mt][nt][1]);
            *(float2*)(C + (size_t)(row + 8) * N + col) =
                make_float2(acc[mt][nt][2], acc[mt][nt][3]);
        }
    }
}

// ---------------- launch ------------------------------------------------------
extern "C" void kernel_launch(void* const* d_in, const int* in_sizes, int n_in,
                              void* d_out, int out_size) {
    const float* x   = (const float*)d_in[0];
    const float* dw  = (const float*)d_in[1];
    const float* db  = (const float*)d_in[2];
    const float* bw1 = (const float*)d_in[3];
    const float* sw1 = (const float*)d_in[4];
    const float* sc1 = (const float*)d_in[5];
    const float* bw2 = (const float*)d_in[6];
    const float* sw2 = (const float*)d_in[7];
    const float* sc2 = (const float*)d_in[8];
    float* out = (float*)d_out;

    float *p_h, *p_phi, *p_Wd, *p_W1, *p_W2;
    cudaGetSymbolAddress((void**)&p_h,   g_h);
    cudaGetSymbolAddress((void**)&p_phi, g_phi);
    cudaGetSymbolAddress((void**)&p_Wd,  g_Wd);
    cudaGetSymbolAddress((void**)&p_W1,  g_W1);
    cudaGetSymbolAddress((void**)&p_W2,  g_W2);

    cudaFuncSetAttribute(gemm_mma, cudaFuncAttributeMaxDynamicSharedMemorySize, SMEM_BYTES);

    prep_dense<<<(LATENT * HID + 255) / 256, 256>>>(dw, p_Wd);
    prep_kan<<<(HID * HID + 255) / 256, 256>>>(bw1, sw1, sc1, p_W1, HID);
    prep_kan<<<(OUTD * HID + 255) / 256, 256>>>(bw2, sw2, sc2, p_W2, OUTD);

    // prelude: h0 = silu(x @ Wd + b)
    sgemm_pre<<<dim3(HID / 128, BATCH / 128), 256>>>(x, p_Wd, db, p_h, BATCH, HID, LATENT);

    int expBlocks = (BATCH * HID + 255) / 256;

    // layer 1
    expand_kernel<<<expBlocks, 256>>>(p_h, p_phi);
    gemm_mma<<<dim3(HID / 256, BATCH / 128), 512, SMEM_BYTES>>>(p_phi, p_W1, p_h, HID);
    // layer 2
    expand_kernel<<<expBlocks, 256>>>(p_h, p_phi);
    gemm_mma<<<dim3(OUTD / 256, BATCH / 128), 512, SMEM_BYTES>>>(p_phi, p_W2, out, OUTD);
}

// round 4
// speedup vs baseline: 3.9744x; 1.4592x over previous
#include <cuda_runtime.h>
#include <cuda_fp16.h>
#include <math.h>
#include <stdint.h>

#define BATCH   16384
#define LATENT  64
#define HID     512
#define OUTD    256
#define KEXP    (HID * 9)    // 4608
#define KCH     64           // K-chunk in halves
#define NCHUNK  (KEXP / KCH) // 72

// ---------------- scratch (device globals; allocation-free rule) ------------
__device__ float  g_h  [(size_t)BATCH * HID];
__device__ __half g_phi[(size_t)BATCH * KEXP];         // fp16 features (151 MB)
__device__ float  g_Wd [(size_t)LATENT * HID];
__device__ __half g_W1 [(size_t)HID  * KEXP];          // layer1 W (N x K, K-major, fp16)
__device__ __half g_W2 [(size_t)OUTD * KEXP];          // layer2 W (N x K, K-major, fp16)

// ---------------- helpers -----------------------------------------------------
__device__ __forceinline__ uint32_t smem_u32(const void* p) {
    uint32_t a;
    asm("{ .reg .u64 t; cvta.to.shared.u64 t, %1; cvt.u32.u64 %0, t; }" : "=r"(a) : "l"(p));
    return a;
}
__device__ __forceinline__ void cp16(uint32_t dst, const void* src) {
    asm volatile("cp.async.cg.shared.global [%0], [%1], 16;" :: "r"(dst), "l"(src));
}
__device__ __forceinline__ void mma_f16(float* d, const uint32_t* a, uint32_t b0, uint32_t b1) {
    asm volatile(
        "mma.sync.aligned.m16n8k16.row.col.f32.f16.f16.f32 "
        "{%0,%1,%2,%3}, {%4,%5,%6,%7}, {%8,%9}, {%0,%1,%2,%3};"
        : "+f"(d[0]), "+f"(d[1]), "+f"(d[2]), "+f"(d[3])
        : "r"(a[0]), "r"(a[1]), "r"(a[2]), "r"(a[3]), "r"(b0), "r"(b1));
}

// ---------------- weight prep ------------------------------------------------
__global__ void prep_dense(const float* __restrict__ dw, float* __restrict__ Wd) {
    int idx = blockIdx.x * blockDim.x + threadIdx.x;
    if (idx >= LATENT * HID) return;
    int k = idx / HID, n = idx % HID;
    Wd[(size_t)k * HID + n] = dw[(size_t)n * LATENT + k];
}
// N x K, K-major, fp16
__global__ void prep_kan(const float* __restrict__ bw, const float* __restrict__ sw,
                         const float* __restrict__ sc, __half* __restrict__ Wt, int N) {
    int idx = blockIdx.x * blockDim.x + threadIdx.x;
    if (idx >= N * HID) return;
    int o = idx / HID, i = idx % HID;
    float s = sc[(size_t)o * HID + i];
    size_t base = (size_t)o * KEXP + (size_t)i * 9;
    Wt[base] = __float2half_rn(bw[(size_t)o * HID + i]);
#pragma unroll
    for (int g = 0; g < 8; g++)
        Wt[base + 1 + g] = __float2half_rn(sw[((size_t)o * HID + i) * 8 + g] * s);
}

// ---------------- expand: h -> [silu(h), B-splines(h)] fp16 -------------------
__global__ void expand_kernel(const float* __restrict__ h, __half* __restrict__ phi) {
    int idx = blockIdx.x * blockDim.x + threadIdx.x;
    if (idx >= BATCH * HID) return;
    float xv = h[idx];

    float g[12];
#pragma unroll
    for (int j = 0; j < 12; j++)
        g[j] = __fadd_rn(__fmul_rn((float)(j - 3), 0.4f), -1.0f);

    float bas[11];
#pragma unroll
    for (int j = 0; j < 11; j++)
        bas[j] = (xv >= g[j] && xv < g[j + 1]) ? 1.0f : 0.0f;
#pragma unroll
    for (int k = 1; k <= 3; k++) {
#pragma unroll
        for (int j = 0; j < 11 - k; j++) {
            float left  = (xv - g[j])         / (g[j + k]     - g[j])     * bas[j];
            float right = (g[j + k + 1] - xv) / (g[j + k + 1] - g[j + 1]) * bas[j + 1];
            bas[j] = left + right;
        }
    }
    float si = xv / (1.0f + expf(-xv));
    size_t base = (size_t)idx * 9;
    phi[base] = __float2half_rn(si);
#pragma unroll
    for (int gg = 0; gg < 8; gg++) phi[base + 1 + gg] = __float2half_rn(bas[gg]);
}

// ---------------- prelude fp32 SGEMM (K=64): C = silu(A*B + bias) ------------
__global__ __launch_bounds__(256) void sgemm_pre(
    const float* __restrict__ A, const float* __restrict__ Bm,
    const float* __restrict__ bias, float* __restrict__ C, int M, int N, int K)
{
    constexpr int BK = 16;
    __shared__ float As[BK][128];
    __shared__ float Bs[BK][128];
    const int tid = threadIdx.x;
    const int tx = tid & 15, ty = tid >> 4;
    const int bm = blockIdx.y * 128, bn = blockIdx.x * 128;
    float acc[8][8];
#pragma unroll
    for (int i = 0; i < 8; i++)
#pragma unroll
        for (int j = 0; j < 8; j++) acc[i][j] = 0.0f;

    for (int k0 = 0; k0 < K; k0 += BK) {
#pragma unroll
        for (int it = 0; it < 2; it++) {
            int f4 = tid + it * 256;
            int ar = f4 >> 2, ac = (f4 & 3) << 2;
            float4 va = *(const float4*)(A + (size_t)(bm + ar) * K + k0 + ac);
            As[ac + 0][ar] = va.x; As[ac + 1][ar] = va.y;
            As[ac + 2][ar] = va.z; As[ac + 3][ar] = va.w;
            int br = f4 >> 5, bc = (f4 & 31) << 2;
            *(float4*)&Bs[br][bc] = *(const float4*)(Bm + (size_t)(k0 + br) * N + bn + bc);
        }
        __syncthreads();
#pragma unroll
        for (int kk = 0; kk < BK; kk++) {
            float a[8], b[8];
#pragma unroll
            for (int i = 0; i < 8; i++) a[i] = As[kk][ty * 8 + i];
#pragma unroll
            for (int j = 0; j < 8; j++) b[j] = Bs[kk][tx * 8 + j];
#pragma unroll
            for (int i = 0; i < 8; i++)
#pragma unroll
                for (int j = 0; j < 8; j++) acc[i][j] += a[i] * b[j];
        }
        __syncthreads();
    }
#pragma unroll
    for (int i = 0; i < 8; i++) {
        int row = bm + ty * 8 + i;
#pragma unroll
        for (int j = 0; j < 8; j++) {
            int col = bn + tx * 8 + j;
            float v = acc[i][j] + bias[col];
            C[(size_t)row * N + col] = v / (1.0f + expf(-v));
        }
    }
}

// ---------------- fp16 mma.sync GEMM: C[M,N] = A[M,K] * W[N,K]^T --------------
// Block 128x256, BK=64 halves, 512 threads (16 warps, 4x4), warp tile 32x64.
// SMEM row pitch: 72 halves = 36 words = 144B (bank-conflict-free fragments).
#define PITCHW  36                        // words per row
#define A_W     (128 * PITCHW)            // 4608 words
#define B_W     (256 * PITCHW)            // 9216 words
#define BUF_W   (A_W + B_W)               // 13824 words
#define SMEM_BYTES (2 * BUF_W * 4)        // 110592

__global__ __launch_bounds__(512, 1) void gemm_mma(
    const __half* __restrict__ A, const __half* __restrict__ W,
    float* __restrict__ C, int N)
{
    extern __shared__ __align__(16) uint32_t smu[];
    const uint32_t sbase = smem_u32(smu);

    const int tid  = threadIdx.x;
    const int wid  = tid >> 5, lane = tid & 31;
    const int g    = lane >> 2, t = lane & 3;
    const int wm   = wid & 3;          // warp row (x32)
    const int wn   = wid >> 2;         // warp col (x64)
    const int bm   = blockIdx.y * 128;
    const int bn   = blockIdx.x * 256;
    const int K    = KEXP;

    // cp.async geometry: 16B = 8 halves per op. A: 128 rows x 8 vec = 1024.
    const int ar0 = tid >> 3,         ac0 = (tid & 7) << 3;          // halves
    const int ar1 = (tid + 512) >> 3, ac1 = ((tid + 512) & 7) << 3;
    const __half* aSrc0 = A + (size_t)(bm + ar0) * K + ac0;
    const __half* aSrc1 = A + (size_t)(bm + ar1) * K + ac1;
    const __half* bSrc[4];
    int bn_[4], bc_[4];
#pragma unroll
    for (int i = 0; i < 4; i++) {
        int v = tid + i * 512;
        bn_[i] = v >> 3; bc_[i] = (v & 7) << 3;
        bSrc[i] = W + (size_t)(bn + bn_[i]) * K + bc_[i];
    }
    const uint32_t aDst0 = (ar0 * PITCHW + (ac0 >> 1)) * 4;          // bytes
    const uint32_t aDst1 = (ar1 * PITCHW + (ac1 >> 1)) * 4;
    uint32_t bDst[4];
#pragma unroll
    for (int i = 0; i < 4; i++) bDst[i] = (A_W + bn_[i] * PITCHW + (bc_[i] >> 1)) * 4;

    float acc[2][8][4];
#pragma unroll
    for (int mt = 0; mt < 2; mt++)
#pragma unroll
        for (int nt = 0; nt < 8; nt++)
#pragma unroll
            for (int i = 0; i < 4; i++) acc[mt][nt][i] = 0.0f;

    // prologue: chunks 0,1
#pragma unroll
    for (int c = 0; c < 2; c++) {
        uint32_t bb = sbase + c * BUF_W * 4;
        cp16(bb + aDst0, aSrc0 + c * KCH);
        cp16(bb + aDst1, aSrc1 + c * KCH);
#pragma unroll
        for (int i = 0; i < 4; i++) cp16(bb + bDst[i], bSrc[i] + c * KCH);
        asm volatile("cp.async.commit_group;");
    }

    for (int c = 0; c < NCHUNK; c++) {
        const int buf = c & 1;
        asm volatile("cp.async.wait_group 1;");
        __syncthreads();

        const int sa = buf * BUF_W;
        const int sb = buf * BUF_W + A_W;
#pragma unroll
        for (int kt = 0; kt < 4; kt++) {
            const int kw = kt * 8 + t;         // word offset within row
            uint32_t a[2][4];
#pragma unroll
            for (int mt = 0; mt < 2; mt++) {
                int r0 = wm * 32 + mt * 16 + g;
                a[mt][0] = smu[sa + r0 * PITCHW + kw];
                a[mt][1] = smu[sa + (r0 + 8) * PITCHW + kw];
                a[mt][2] = smu[sa + r0 * PITCHW + kw + 4];
                a[mt][3] = smu[sa + (r0 + 8) * PITCHW + kw + 4];
            }
#pragma unroll
            for (int nt = 0; nt < 8; nt++) {
                int n0 = wn * 64 + nt * 8 + g;
                uint32_t b0 = smu[sb + n0 * PITCHW + kw];
                uint32_t b1 = smu[sb + n0 * PITCHW + kw + 4];
                mma_f16(acc[0][nt], a[0], b0, b1);
                mma_f16(acc[1][nt], a[1], b0, b1);
            }
        }
        __syncthreads();

        if (c + 2 < NCHUNK) {
            uint32_t bb = sbase + buf * BUF_W * 4;
            int off = (c + 2) * KCH;
            cp16(bb + aDst0, aSrc0 + off);
            cp16(bb + aDst1, aSrc1 + off);
#pragma unroll
            for (int i = 0; i < 4; i++) cp16(bb + bDst[i], bSrc[i] + off);
        }
        asm volatile("cp.async.commit_group;");
    }

    // epilogue
#pragma unroll
    for (int mt = 0; mt < 2; mt++) {
        int row = bm + wm * 32 + mt * 16 + g;
#pragma unroll
        for (int nt = 0; nt < 8; nt++) {
            int col = bn + wn * 64 + nt * 8 + 2 * t;
            *(float2*)(C + (size_t)row * N + col) =
                make_float2(acc[mt][nt][0], acc[mt][nt][1]);
            *(float2*)(C + (size_t)(row + 8) * N + col) =
                make_float2(acc[mt][nt][2], acc[mt][nt][3]);
        }
    }
}

// ---------------- launch ------------------------------------------------------
extern "C" void kernel_launch(void* const* d_in, const int* in_sizes, int n_in,
                              void* d_out, int out_size) {
    const float* x   = (const float*)d_in[0];
    const float* dw  = (const float*)d_in[1];
    const float* db  = (const float*)d_in[2];
    const float* bw1 = (const float*)d_in[3];
    const float* sw1 = (const float*)d_in[4];
    const float* sc1 = (const float*)d_in[5];
    const float* bw2 = (const float*)d_in[6];
    const float* sw2 = (const float*)d_in[7];
    const float* sc2 = (const float*)d_in[8];
    float* out = (float*)d_out;

    float  *p_h, *p_Wd;
    __half *p_phi, *p_W1, *p_W2;
    cudaGetSymbolAddress((void**)&p_h,   g_h);
    cudaGetSymbolAddress((void**)&p_phi, g_phi);
    cudaGetSymbolAddress((void**)&p_Wd,  g_Wd);
    cudaGetSymbolAddress((void**)&p_W1,  g_W1);
    cudaGetSymbolAddress((void**)&p_W2,  g_W2);

    cudaFuncSetAttribute(gemm_mma, cudaFuncAttributeMaxDynamicSharedMemorySize, SMEM_BYTES);

    prep_dense<<<(LATENT * HID + 255) / 256, 256>>>(dw, p_Wd);
    prep_kan<<<(HID * HID + 255) / 256, 256>>>(bw1, sw1, sc1, p_W1, HID);
    prep_kan<<<(OUTD * HID + 255) / 256, 256>>>(bw2, sw2, sc2, p_W2, OUTD);

    // prelude: h0 = silu(x @ Wd + b)
    sgemm_pre<<<dim3(HID / 128, BATCH / 128), 256>>>(x, p_Wd, db, p_h, BATCH, HID, LATENT);

    int expBlocks = (BATCH * HID + 255) / 256;

    // layer 1
    expand_kernel<<<expBlocks, 256>>>(p_h, p_phi);
    gemm_mma<<<dim3(HID / 256, BATCH / 128), 512, SMEM_BYTES>>>(p_phi, p_W1, p_h, HID);
    // layer 2
    expand_kernel<<<expBlocks, 256>>>(p_h, p_phi);
    gemm_mma<<<dim3(OUTD / 256, BATCH / 128), 512, SMEM_BYTES>>>(p_phi, p_W2, out, OUTD);
}

// round 5
// speedup vs baseline: 4.0986x; 1.0313x over previous
#include <cuda_runtime.h>
#include <cuda_fp16.h>
#include <math.h>
#include <stdint.h>

#define BATCH   16384
#define LATENT  64
#define HID     512
#define OUTD    256
#define KEXP    (HID * 9)    // 4608
#define KCH     64           // K-chunk in halves
#define NCH_L   (KEXP / KCH) // 72 chunks for KAN layers

// ---------------- scratch (device globals; allocation-free rule) ------------
__device__ float  g_h  [(size_t)BATCH * HID];
__device__ __half g_phi[(size_t)BATCH * KEXP];
__device__ __half g_xh [(size_t)BATCH * LATENT];
__device__ __half g_Wdh[(size_t)HID * LATENT];          // dense_w fp16 (N x K)
__device__ __half g_W1 [(size_t)HID  * KEXP];           // layer1 W (N x K, fp16)
__device__ __half g_W2 [(size_t)OUTD * KEXP];           // layer2 W (N x K, fp16)

// ---------------- helpers -----------------------------------------------------
__device__ __forceinline__ uint32_t smem_u32(const void* p) {
    uint32_t a;
    asm("{ .reg .u64 t; cvta.to.shared.u64 t, %1; cvt.u32.u64 %0, t; }" : "=r"(a) : "l"(p));
    return a;
}
__device__ __forceinline__ void cp16(uint32_t dst, const void* src) {
    asm volatile("cp.async.cg.shared.global [%0], [%1], 16;" :: "r"(dst), "l"(src));
}
__device__ __forceinline__ void ldm_x4(uint32_t* r, uint32_t addr) {
    asm volatile("ldmatrix.sync.aligned.m8n8.x4.shared.b16 {%0,%1,%2,%3}, [%4];"
        : "=r"(r[0]), "=r"(r[1]), "=r"(r[2]), "=r"(r[3]) : "r"(addr));
}
__device__ __forceinline__ void mma_f16(float* d, const uint32_t* a, uint32_t b0, uint32_t b1) {
    asm volatile(
        "mma.sync.aligned.m16n8k16.row.col.f32.f16.f16.f32 "
        "{%0,%1,%2,%3}, {%4,%5,%6,%7}, {%8,%9}, {%0,%1,%2,%3};"
        : "+f"(d[0]), "+f"(d[1]), "+f"(d[2]), "+f"(d[3])
        : "r"(a[0]), "r"(a[1]), "r"(a[2]), "r"(a[3]), "r"(b0), "r"(b1));
}

// ---------------- prep kernels ------------------------------------------------
__global__ void prep_xh(const float* __restrict__ x, __half* __restrict__ xh, int n) {
    int i = blockIdx.x * blockDim.x + threadIdx.x;
    if (i < n) xh[i] = __float2half_rn(x[i]);
}
__global__ void prep_kan(const float* __restrict__ bw, const float* __restrict__ sw,
                         const float* __restrict__ sc, __half* __restrict__ Wt, int N) {
    int idx = blockIdx.x * blockDim.x + threadIdx.x;
    if (idx >= N * HID) return;
    int o = idx / HID, i = idx % HID;
    float s = sc[(size_t)o * HID + i];
    size_t base = (size_t)o * KEXP + (size_t)i * 9;
    Wt[base] = __float2half_rn(bw[(size_t)o * HID + i]);
#pragma unroll
    for (int g = 0; g < 8; g++)
        Wt[base + 1 + g] = __float2half_rn(sw[((size_t)o * HID + i) * 8 + g] * s);
}

// ---------------- expand: h -> [silu(h), B-splines(h)] fp16 -------------------
__global__ void expand_kernel(const float* __restrict__ h, __half* __restrict__ phi) {
    int idx = blockIdx.x * blockDim.x + threadIdx.x;
    if (idx >= BATCH * HID) return;
    float xv = h[idx];

    float g[12];
#pragma unroll
    for (int j = 0; j < 12; j++)
        g[j] = __fadd_rn(__fmul_rn((float)(j - 3), 0.4f), -1.0f);

    float bas[11];
#pragma unroll
    for (int j = 0; j < 11; j++)
        bas[j] = (xv >= g[j] && xv < g[j + 1]) ? 1.0f : 0.0f;
#pragma unroll
    for (int k = 1; k <= 3; k++) {
#pragma unroll
        for (int j = 0; j < 11 - k; j++) {
            float left  = (xv - g[j])         / (g[j + k]     - g[j])     * bas[j];
            float right = (g[j + k + 1] - xv) / (g[j + k + 1] - g[j + 1]) * bas[j + 1];
            bas[j] = left + right;
        }
    }
    float si = xv / (1.0f + expf(-xv));
    size_t base = (size_t)idx * 9;
    phi[base] = __float2half_rn(si);
#pragma unroll
    for (int gg = 0; gg < 8; gg++) phi[base + 1 + gg] = __float2half_rn(bas[gg]);
}

// ---------------- fp16 mma GEMM: C[M,N] = A[M,K] * W[N,K]^T -------------------
// Block 128x256, BK=64 halves, 512 threads (16 warps, 4x4), warp tile 32x64.
// 3-stage cp.async pipeline, one __syncthreads per chunk, ldmatrix fragments.
// EPI==1: C = silu(acc + bias[col]).
#define PITCHW  36                        // words per smem row (32 data + 4 pad)
#define A_W     (128 * PITCHW)
#define B_W     (256 * PITCHW)
#define BUF_W   (A_W + B_W)               // 13824 words
#define SMEM_BYTES (3 * BUF_W * 4)        // 165888

template <int NCHUNK_T, int EPI>
__global__ __launch_bounds__(512, 1) void gemm_mma(
    const __half* __restrict__ A, const __half* __restrict__ W,
    const float* __restrict__ bias, float* __restrict__ C, int N)
{
    constexpr int K = NCHUNK_T * KCH;
    extern __shared__ __align__(16) uint32_t smu[];
    const uint32_t sbase = smem_u32(smu);

    const int tid  = threadIdx.x;
    const int wid  = tid >> 5, lane = tid & 31;
    const int wm   = wid & 3;          // warp row (x32)
    const int wn   = wid >> 2;         // warp col (x64)
    const int bm   = blockIdx.y * 128;
    const int bn   = blockIdx.x * 256;

    // ldmatrix lane addressing: lane l -> row (l&15), k-byte (l>>4)*16
    const uint32_t laneRow = lane & 15;
    const uint32_t laneKB  = (lane >> 4) * 16;
    const uint32_t aLaneOff = (wm * 32 + laneRow) * (PITCHW * 4) + laneKB;
    const uint32_t bLaneOff = A_W * 4 + (wn * 64 + laneRow) * (PITCHW * 4) + laneKB;

    // cp.async geometry (16B = 8 halves). A: 1024 vecs, B: 2048 vecs.
    const int ar0 = tid >> 3,         ac0 = (tid & 7) << 3;
    const int ar1 = (tid + 512) >> 3, ac1 = ((tid + 512) & 7) << 3;
    const __half* aSrc0 = A + (size_t)(bm + ar0) * K + ac0;
    const __half* aSrc1 = A + (size_t)(bm + ar1) * K + ac1;
    const __half* bSrc[4];
    int bn_[4], bc_[4];
#pragma unroll
    for (int i = 0; i < 4; i++) {
        int v = tid + i * 512;
        bn_[i] = v >> 3; bc_[i] = (v & 7) << 3;
        bSrc[i] = W + (size_t)(bn + bn_[i]) * K + bc_[i];
    }
    const uint32_t aDst0 = (ar0 * PITCHW + (ac0 >> 1)) * 4;
    const uint32_t aDst1 = (ar1 * PITCHW + (ac1 >> 1)) * 4;
    uint32_t bDst[4];
#pragma unroll
    for (int i = 0; i < 4; i++) bDst[i] = (A_W + bn_[i] * PITCHW + (bc_[i] >> 1)) * 4;

    float acc[2][8][4];
#pragma unroll
    for (int mt = 0; mt < 2; mt++)
#pragma unroll
        for (int nt = 0; nt < 8; nt++)
#pragma unroll
            for (int i = 0; i < 4; i++) acc[mt][nt][i] = 0.0f;

    // prologue: stage chunks 0,1 into buffers 0,1
#pragma unroll
    for (int c = 0; c < 2; c++) {
        if (c < NCHUNK_T) {
            uint32_t bb = sbase + c * BUF_W * 4;
            cp16(bb + aDst0, aSrc0 + c * KCH);
            cp16(bb + aDst1, aSrc1 + c * KCH);
#pragma unroll
            for (int i = 0; i < 4; i++) cp16(bb + bDst[i], bSrc[i] + c * KCH);
        }
        asm volatile("cp.async.commit_group;");
    }

    int buf = 0, nbuf = 2;
    for (int c = 0; c < NCHUNK_T; c++) {
        asm volatile("cp.async.wait_group 1;");
        __syncthreads();

        // issue loads for chunk c+2 into buffer (c+2)%3
        if (c + 2 < NCHUNK_T) {
            uint32_t bb = sbase + nbuf * BUF_W * 4;
            int off = (c + 2) * KCH;
            cp16(bb + aDst0, aSrc0 + off);
            cp16(bb + aDst1, aSrc1 + off);
#pragma unroll
            for (int i = 0; i < 4; i++) cp16(bb + bDst[i], bSrc[i] + off);
        }
        asm volatile("cp.async.commit_group;");

        const uint32_t base = sbase + buf * BUF_W * 4;
#pragma unroll
        for (int kt = 0; kt < 4; kt++) {
            uint32_t a[2][4], b[4][4];
            ldm_x4(a[0], base + aLaneOff + kt * 32);
            ldm_x4(a[1], base + aLaneOff + 16 * PITCHW * 4 + kt * 32);
#pragma unroll
            for (int p = 0; p < 4; p++)
                ldm_x4(b[p], base + bLaneOff + p * 16 * PITCHW * 4 + kt * 32);
#pragma unroll
            for (int p = 0; p < 4; p++) {
                // frag pair p covers nt = 2p (b[p][0], b[p][2]) and 2p+1 (b[p][1], b[p][3])
                mma_f16(acc[0][2 * p],     a[0], b[p][0], b[p][2]);
                mma_f16(acc[1][2 * p],     a[1], b[p][0], b[p][2]);
                mma_f16(acc[0][2 * p + 1], a[0], b[p][1], b[p][3]);
                mma_f16(acc[1][2 * p + 1], a[1], b[p][1], b[p][3]);
            }
        }
        buf = (buf + 1 == 3) ? 0 : buf + 1;
        nbuf = (nbuf + 1 == 3) ? 0 : nbuf + 1;
    }

    // epilogue
    const int g = lane >> 2, t = lane & 3;
#pragma unroll
    for (int mt = 0; mt < 2; mt++) {
        int row = bm + wm * 32 + mt * 16 + g;
#pragma unroll
        for (int nt = 0; nt < 8; nt++) {
            int col = bn + wn * 64 + nt * 8 + 2 * t;
#pragma unroll
            for (int hrow = 0; hrow < 2; hrow++) {
                float v0 = acc[mt][nt][2 * hrow + 0];
                float v1 = acc[mt][nt][2 * hrow + 1];
                if (EPI == 1) {
                    v0 += bias[col];     v1 += bias[col + 1];
                    v0 = v0 / (1.0f + expf(-v0));
                    v1 = v1 / (1.0f + expf(-v1));
                }
                *(float2*)(C + (size_t)(row + 8 * hrow) * N + col) = make_float2(v0, v1);
            }
        }
    }
}

// ---------------- launch ------------------------------------------------------
extern "C" void kernel_launch(void* const* d_in, const int* in_sizes, int n_in,
                              void* d_out, int out_size) {
    const float* x   = (const float*)d_in[0];
    const float* dw  = (const float*)d_in[1];
    const float* db  = (const float*)d_in[2];
    const float* bw1 = (const float*)d_in[3];
    const float* sw1 = (const float*)d_in[4];
    const float* sc1 = (const float*)d_in[5];
    const float* bw2 = (const float*)d_in[6];
    const float* sw2 = (const float*)d_in[7];
    const float* sc2 = (const float*)d_in[8];
    float* out = (float*)d_out;

    float  *p_h;
    __half *p_phi, *p_xh, *p_Wdh, *p_W1, *p_W2;
    cudaGetSymbolAddress((void**)&p_h,   g_h);
    cudaGetSymbolAddress((void**)&p_phi, g_phi);
    cudaGetSymbolAddress((void**)&p_xh,  g_xh);
    cudaGetSymbolAddress((void**)&p_Wdh, g_Wdh);
    cudaGetSymbolAddress((void**)&p_W1,  g_W1);
    cudaGetSymbolAddress((void**)&p_W2,  g_W2);

    cudaFuncSetAttribute(gemm_mma<NCH_L, 0>, cudaFuncAttributeMaxDynamicSharedMemorySize, SMEM_BYTES);
    cudaFuncSetAttribute(gemm_mma<1, 1>,     cudaFuncAttributeMaxDynamicSharedMemorySize, SMEM_BYTES);

    // preps
    prep_xh<<<(BATCH * LATENT + 255) / 256, 256>>>(x, p_xh, BATCH * LATENT);
    prep_xh<<<(HID * LATENT + 255) / 256, 256>>>(dw, p_Wdh, HID * LATENT);  // (N,K) layout as-is
    prep_kan<<<(HID * HID + 255) / 256, 256>>>(bw1, sw1, sc1, p_W1, HID);
    prep_kan<<<(OUTD * HID + 255) / 256, 256>>>(bw2, sw2, sc2, p_W2, OUTD);

    // prelude: h0 = silu(x @ dense_w^T + b)   (K = 64 -> 1 chunk)
    gemm_mma<1, 1><<<dim3(HID / 256, BATCH / 128), 512, SMEM_BYTES>>>(
        p_xh, p_Wdh, db, p_h, HID);

    int expBlocks = (BATCH * HID + 255) / 256;

    // layer 1
    expand_kernel<<<expBlocks, 256>>>(p_h, p_phi);
    gemm_mma<NCH_L, 0><<<dim3(HID / 256, BATCH / 128), 512, SMEM_BYTES>>>(
        p_phi, p_W1, nullptr, p_h, HID);
    // layer 2
    expand_kernel<<<expBlocks, 256>>>(p_h, p_phi);
    gemm_mma<NCH_L, 0><<<dim3(OUTD / 256, BATCH / 128), 512, SMEM_BYTES>>>(
        p_phi, p_W2, nullptr, out, OUTD);
}